// round 12
// baseline (speedup 1.0000x reference)
#include <cuda_runtime.h>
#include <cuda_fp16.h>
#include <cstdint>

#define NN 50000
#define KNBR 16

// ---------------- scratch (device globals; no runtime allocation) ----------------
__device__ __align__(16) __half g_B1h[128 * 128];     // [n][k] halves: W1 = [We1|Ws1]^T
__device__ __align__(16) __half g_B2h[128 * 128];     // [n][k] halves
__device__ __align__(16) float  g_zs[2 * NN * 64];    // xs (self transform), fp32
__device__ __align__(16) float  g_ys[2 * NN * 64];    // ys, fp32
__device__ __align__(16) __half g_zn_h[2 * NN * 64];  // xn fp16 (gather operand)
__device__ __align__(16) __half g_yn_h[2 * NN * 64];  // yn fp16 (gather operand)
__device__ __align__(16) __half g_h_h[2 * NN * 128];  // h = sigmoid(cat(xs,aggr)), fp16
__device__ __align__(16) __half g_aggr_h[2 * NN * 64];
__device__ __align__(8)  float2 g_scal[2 * NN];       // {nsq, sj} packed -> 1 LDG.64 gather
__device__ float g_si[2 * NN];
__device__ float g_norm[2 * NN * KNBR];

__device__ __forceinline__ float sigmoidf_(float x) { return 1.f / (1.f + __expf(-x)); }

__device__ __forceinline__ void mma_f16(float* d, const uint32_t* a, uint32_t b0, uint32_t b1) {
    asm volatile(
        "mma.sync.aligned.m16n8k16.row.col.f32.f16.f16.f32 "
        "{%0,%1,%2,%3}, {%4,%5,%6,%7}, {%8,%9}, {%0,%1,%2,%3};"
        : "+f"(d[0]), "+f"(d[1]), "+f"(d[2]), "+f"(d[3])
        : "r"(a[0]), "r"(a[1]), "r"(a[2]), "r"(a[3]), "r"(b0), "r"(b1));
}

__device__ __forceinline__ void ldm_x4(uint32_t* r, const uint32_t* p) {
    uint32_t addr = (uint32_t)__cvta_generic_to_shared(p);
    asm volatile("ldmatrix.sync.aligned.m8n8.x4.shared.b16 {%0,%1,%2,%3}, [%4];"
                 : "=r"(r[0]), "=r"(r[1]), "=r"(r[2]), "=r"(r[3]) : "r"(addr));
}

__device__ __forceinline__ void cp16(uint32_t smem_addr, const void* gptr) {
    asm volatile("cp.async.ca.shared.global [%0], [%1], 16;" :: "r"(smem_addr), "l"(gptr));
}

// ---------------- pack W -> [n][k] fp16 ----------------
__global__ void pack_B_kernel(const float* __restrict__ We1, const float* __restrict__ Ws1,
                              const float* __restrict__ We2, const float* __restrict__ Ws2) {
    int idx = blockIdx.x * blockDim.x + threadIdx.x;
    if (idx >= 128 * 128) return;
    int n = idx >> 7, k = idx & 127;
    float v1 = (n < 64) ? We1[k * 64 + n] : Ws1[k * 64 + (n - 64)];
    float v2 = (n < 64) ? We2[k * 64 + n] : Ws2[k * 64 + (n - 64)];
    g_B1h[idx] = __float2half_rn(v1);
    g_B2h[idx] = __float2half_rn(v2);
}

// ---------------- fp16 tensor-core GEMM: C[M,128] = A[M,128] @ B[128,128] ----------------
// Full K resident; 256 threads = 8 warps (4m x 2n); warp tile 32x64. (R8-frozen)
#define AG 68
#define GEMM_SMEM (2 * 128 * AG * 4)

__global__ void __launch_bounds__(256) gemm_tc(const float* __restrict__ x1,
                                               const float* __restrict__ x2, int layer) {
    extern __shared__ uint32_t smg[];
    uint32_t* As = smg;                 // [128 rows][AG words]
    uint32_t* Bs = smg + 128 * AG;      // [128 n][AG words]

    const int Mtot = 2 * NN;
    const __half* __restrict__ Bg = (layer == 1) ? g_B1h : g_B2h;
    float*  __restrict__ Cs = (layer == 1) ? g_zs : g_ys;
    __half* __restrict__ Ch = (layer == 1) ? g_zn_h : g_yn_h;

    int tid = threadIdx.x;
    int rowBase = blockIdx.x * 128;

    // ---- load A tile ----
    if (layer == 1) {
#pragma unroll
        for (int it = 0; it < 16; it++) {
            int row = (tid >> 5) + it * 8;
            int f4 = tid & 31;
            int grow = rowBase + row;
            float4 v = {0.f, 0.f, 0.f, 0.f};
            if (grow < Mtot) {
                const float* src = (grow < NN) ? (x1 + (size_t)grow * 128)
                                               : (x2 + (size_t)(grow - NN) * 128);
                v = *(const float4*)(src + f4 * 4);
            }
            __half2 w0 = __floats2half2_rn(v.x, v.y);
            __half2 w1 = __floats2half2_rn(v.z, v.w);
            uint2 w = {*(uint32_t*)&w0, *(uint32_t*)&w1};
            *(uint2*)&As[row * AG + f4 * 2] = w;
        }
    } else {
#pragma unroll
        for (int it = 0; it < 8; it++) {
            int row = (tid >> 4) + it * 16;
            int c = tid & 15;
            int grow = rowBase + row;
            uint4 v = {0, 0, 0, 0};
            if (grow < Mtot) v = *(const uint4*)&g_h_h[(size_t)grow * 128 + c * 8];
            *(uint4*)&As[row * AG + c * 4] = v;
        }
    }
    // ---- load B tile [n][k] ----
#pragma unroll
    for (int it = 0; it < 8; it++) {
        int n = (tid >> 4) + it * 16;
        int c = tid & 15;
        uint4 v = *(const uint4*)&Bg[(size_t)n * 128 + c * 8];
        *(uint4*)&Bs[n * AG + c * 4] = v;
    }
    __syncthreads();

    int lane = tid & 31;
    int wm = (tid >> 5) & 3;
    int wn = tid >> 7;
    int lr = lane & 7, lg = lane >> 3;

    float acc[2][8][4];
#pragma unroll
    for (int mf = 0; mf < 2; mf++)
#pragma unroll
        for (int nf = 0; nf < 8; nf++)
#pragma unroll
            for (int c = 0; c < 4; c++) acc[mf][nf][c] = 0.f;

#pragma unroll
    for (int ks = 0; ks < 8; ks++) {
        int kb = ks * 8;
        uint32_t a[2][4];
#pragma unroll
        for (int mf = 0; mf < 2; mf++) {
            int row = wm * 32 + mf * 16 + lr + (lg & 1) * 8;
            int word = kb + (lg >> 1) * 4;
            ldm_x4(a[mf], &As[row * AG + word]);
        }
        uint32_t b[8][2];
#pragma unroll
        for (int p = 0; p < 4; p++) {
            int n = wn * 64 + p * 16 + lr + (lg >> 1) * 8;
            int word = kb + (lg & 1) * 4;
            ldm_x4(&b[2 * p][0], &Bs[n * AG + word]);
        }
#pragma unroll
        for (int mf = 0; mf < 2; mf++)
#pragma unroll
            for (int nf = 0; nf < 8; nf++)
                mma_f16(acc[mf][nf], a[mf], b[nf][0], b[nf][1]);
    }

    // ---- epilogue: cols<64 -> fp16 (gather operand); cols>=64 -> fp32 self buffer ----
    int rq = lane >> 2, kq = lane & 3;
#pragma unroll
    for (int mf = 0; mf < 2; mf++) {
#pragma unroll
        for (int nf = 0; nf < 8; nf++) {
            int row = rowBase + wm * 32 + mf * 16 + rq;
            int col = nf * 8 + kq * 2;            // 0..63 within the wn half
            if (wn == 0) {
                if (row < Mtot) {
                    __half2 h = __floats2half2_rn(acc[mf][nf][0], acc[mf][nf][1]);
                    *(uint32_t*)&Ch[(size_t)row * 64 + col] = *(uint32_t*)&h;
                }
                if (row + 8 < Mtot) {
                    __half2 h = __floats2half2_rn(acc[mf][nf][2], acc[mf][nf][3]);
                    *(uint32_t*)&Ch[(size_t)(row + 8) * 64 + col] = *(uint32_t*)&h;
                }
            } else {
                if (row < Mtot) {
                    float2 v = {acc[mf][nf][0], acc[mf][nf][1]};
                    *(float2*)&Cs[(size_t)row * 64 + col] = v;
                }
                if (row + 8 < Mtot) {
                    float2 v = {acc[mf][nf][2], acc[mf][nf][3]};
                    *(float2*)&Cs[(size_t)(row + 8) * 64 + col] = v;
                }
            }
        }
    }
}

// ---------------- layer-1 aggregate + h + attention scalars ----------------
__global__ void aggr_kernel(const int* __restrict__ nbr1, const int* __restrict__ nbr2,
                            const float* __restrict__ watt) {
    int t = threadIdx.x;
    int nodeLocal = t >> 4;
    int q = t & 15;
    int node = blockIdx.x * 16 + nodeLocal;
    int g = node >= NN;
    int i = g ? node - NN : node;
    const int* nbr = g ? nbr2 : nbr1;
    size_t gbase = (size_t)g * NN;

    int nid = __ldg(&nbr[i * 16 + q]);

    float4 s = {0.f, 0.f, 0.f, 0.f};
#pragma unroll
    for (int k = 0; k < 16; k++) {
        int j = __shfl_sync(0xffffffffu, nid, k, 16);
        uint2 raw = *(const uint2*)&g_zn_h[(gbase + j) * 64 + q * 4];
        float2 lo = __half22float2(*(__half2*)&raw.x);
        float2 hi = __half22float2(*(__half2*)&raw.y);
        s.x += lo.x; s.y += lo.y; s.z += hi.x; s.w += hi.y;
    }
    s.x *= (1.f / 16.f); s.y *= (1.f / 16.f); s.z *= (1.f / 16.f); s.w *= (1.f / 16.f);

    __half2 h0 = __floats2half2_rn(s.x, s.y);
    __half2 h1 = __floats2half2_rn(s.z, s.w);
    uint2 packed = {*(uint32_t*)&h0, *(uint32_t*)&h1};
    *(uint2*)&g_aggr_h[(size_t)node * 64 + q * 4] = packed;
    float2 r0 = __half22float2(h0);
    float2 r1 = __half22float2(h1);

    float4 xs = *(const float4*)&g_zs[(size_t)node * 64 + q * 4];
    __half2 hx0 = __floats2half2_rn(sigmoidf_(xs.x), sigmoidf_(xs.y));
    __half2 hx1 = __floats2half2_rn(sigmoidf_(xs.z), sigmoidf_(xs.w));
    __half2 ha0 = __floats2half2_rn(sigmoidf_(s.x), sigmoidf_(s.y));
    __half2 ha1 = __floats2half2_rn(sigmoidf_(s.z), sigmoidf_(s.w));
    uint2 px = {*(uint32_t*)&hx0, *(uint32_t*)&hx1};
    uint2 pa = {*(uint32_t*)&ha0, *(uint32_t*)&ha1};
    *(uint2*)&g_h_h[(size_t)node * 128 + q * 4] = px;
    *(uint2*)&g_h_h[(size_t)node * 128 + 64 + q * 4] = pa;

    float4 w0 = *(const float4*)&watt[q * 4];
    float4 w1 = *(const float4*)&watt[64 + q * 4];
    float p0 = s.x * w0.x + s.y * w0.y + s.z * w0.z + s.w * w0.w;
    float p1 = s.x * w1.x + s.y * w1.y + s.z * w1.z + s.w * w1.w;
    float p2 = r0.x * r0.x + r0.y * r0.y + r1.x * r1.x + r1.y * r1.y;
#pragma unroll
    for (int o = 8; o; o >>= 1) {
        p0 += __shfl_xor_sync(0xffffffffu, p0, o);
        p1 += __shfl_xor_sync(0xffffffffu, p1, o);
        p2 += __shfl_xor_sync(0xffffffffu, p2, o);
    }
    if (q == 0) {
        g_si[node] = p0;
        g_scal[node] = make_float2(p2, p1);   // {nsq, sj}
    }
}

// ---------------- cross-attn + self-attn via f16 tensor-core Gram ----------------
// 2 nodes per warp, double-buffered cp.async groups: node1's gather overlaps
// node0's compute. 4 warps/block -> 8 nodes/block; grid = NN/8.
#define ATW 36

__device__ __forceinline__ void attn_compute(const uint32_t* tile, float2 sc, float sii,
                                             int i, int lane) {
    const uint32_t* a1s = tile;
    const uint32_t* a2s = tile + 16 * ATW;
    float myNsq = sc.x;

    int rq = lane >> 2;
    int kq = lane & 3;
    int lr = lane & 7, lg = lane >> 3;
    float acc[2][4];
#pragma unroll
    for (int nt = 0; nt < 2; nt++)
#pragma unroll
        for (int c = 0; c < 4; c++) acc[nt][c] = 0.f;

#pragma unroll
    for (int ks = 0; ks < 4; ks++) {
        int kb = ks * 8;
        uint32_t a[4], b[2][2];
        ldm_x4(a, &a1s[(lr + (lg & 1) * 8) * ATW + kb + (lg >> 1) * 4]);
        ldm_x4(&b[0][0], &a2s[(lr + (lg >> 1) * 8) * ATW + kb + (lg & 1) * 4]);
        mma_f16(acc[0], a, b[0][0], b[0][1]);
        mma_f16(acc[1], a, b[1][0], b[1][1]);
    }

    float nsqK0 = __shfl_sync(0xffffffffu, myNsq, rq);
    float nsqK1 = __shfl_sync(0xffffffffu, myNsq, rq + 8);
    float rp0 = 0.f, rp1 = 0.f;
    float cp[2][2];
#pragma unroll
    for (int nt = 0; nt < 2; nt++) {
        float nsqL0 = __shfl_sync(0xffffffffu, myNsq, 16 + nt * 8 + 2 * kq);
        float nsqL1 = __shfl_sync(0xffffffffu, myNsq, 16 + nt * 8 + 2 * kq + 1);
        float s00 = __expf(-sqrtf(fmaxf(nsqK0 + nsqL0 - 2.f * acc[nt][0], 1e-12f)));
        float s01 = __expf(-sqrtf(fmaxf(nsqK0 + nsqL1 - 2.f * acc[nt][1], 1e-12f)));
        float s10 = __expf(-sqrtf(fmaxf(nsqK1 + nsqL0 - 2.f * acc[nt][2], 1e-12f)));
        float s11 = __expf(-sqrtf(fmaxf(nsqK1 + nsqL1 - 2.f * acc[nt][3], 1e-12f)));
        rp0 += s00 + s01;
        rp1 += s10 + s11;
        cp[nt][0] = s00 + s10;
        cp[nt][1] = s01 + s11;
    }

    rp0 += __shfl_xor_sync(0xffffffffu, rp0, 1);
    rp1 += __shfl_xor_sync(0xffffffffu, rp1, 1);
    rp0 += __shfl_xor_sync(0xffffffffu, rp0, 2);
    rp1 += __shfl_xor_sync(0xffffffffu, rp1, 2);
    float tot = rp0 + rp1;
#pragma unroll
    for (int o = 4; o <= 16; o <<= 1) tot += __shfl_xor_sync(0xffffffffu, tot, o);
#pragma unroll
    for (int o = 4; o <= 16; o <<= 1) {
        cp[0][0] += __shfl_xor_sync(0xffffffffu, cp[0][0], o);
        cp[0][1] += __shfl_xor_sync(0xffffffffu, cp[0][1], o);
        cp[1][0] += __shfl_xor_sync(0xffffffffu, cp[1][0], o);
        cp[1][1] += __shfl_xor_sync(0xffffffffu, cp[1][1], o);
    }

    int kl = lane & 15;
    float r0v = __shfl_sync(0xffffffffu, rp0, 4 * (kl & 7));
    float r1v = __shfl_sync(0xffffffffu, rp1, 4 * (kl & 7));
    float rowval = (kl < 8) ? r0v : r1v;
    int srcC = (kl & 7) >> 1;
    float c00 = __shfl_sync(0xffffffffu, cp[0][0], srcC);
    float c01 = __shfl_sync(0xffffffffu, cp[0][1], srcC);
    float c10 = __shfl_sync(0xffffffffu, cp[1][0], srcC);
    float c11 = __shfl_sync(0xffffffffu, cp[1][1], srcC);
    float colval = (kl >> 3) ? ((kl & 1) ? c11 : c10) : ((kl & 1) ? c01 : c00);

    float cross = ((lane < 16) ? rowval : colval) / tot;

    float sjv = sc.y;
    float zz = sii + sjv;
    float lr2 = (zz >= 0.f) ? zz : 0.01f * zz;
    float e = __expf(lr2);
    float esum = e;
#pragma unroll
    for (int o = 8; o; o >>= 1) esum += __shfl_xor_sync(0xffffffffu, esum, o);

    float nrm = cross * (e / esum);
    if (lane < 16) g_norm[(size_t)i * 16 + lane] = nrm;
    else           g_norm[(size_t)(NN + i) * 16 + (lane - 16)] = nrm;
}

__global__ void __launch_bounds__(128) attn_kernel(const int* __restrict__ nbr1,
                                                   const int* __restrict__ nbr2) {
    __shared__ uint32_t sm[4][2][2 * 16 * ATW];
    int warp = threadIdx.x >> 5;
    int lane = threadIdx.x & 31;
    int i0 = blockIdx.x * 8 + warp * 2;
    int i1 = i0 + 1;

    int nid0, nid1;
    if (lane < 16) {
        nid0 = nbr1[i0 * 16 + lane];
        nid1 = nbr1[i1 * 16 + lane];
    } else {
        nid0 = nbr2[i0 * 16 + (lane - 16)];
        nid1 = nbr2[i1 * 16 + (lane - 16)];
    }
    int gnid0 = (lane < 16) ? nid0 : NN + nid0;
    int gnid1 = (lane < 16) ? nid1 : NN + nid1;

    uint32_t sb0 = (uint32_t)__cvta_generic_to_shared(sm[warp][0]);
    uint32_t sb1 = (uint32_t)__cvta_generic_to_shared(sm[warp][1]);

    // ---- gather node0 (group 0) ----
#pragma unroll
    for (int it = 0; it < 8; it++) {
        int idx = it * 32 + lane;
        int arr = idx >> 7;
        int local = idx & 127;
        int row = local >> 3, d4 = local & 7;
        int j = __shfl_sync(0xffffffffu, nid0, arr * 16 + row);
        cp16(sb0 + (uint32_t)(arr * 16 * ATW + row * ATW + d4 * 4) * 4,
             (const char*)g_aggr_h + ((size_t)(arr ? NN : 0) + j) * 128 + d4 * 16);
    }
    asm volatile("cp.async.commit_group;");
    // ---- gather node1 (group 1) ----
#pragma unroll
    for (int it = 0; it < 8; it++) {
        int idx = it * 32 + lane;
        int arr = idx >> 7;
        int local = idx & 127;
        int row = local >> 3, d4 = local & 7;
        int j = __shfl_sync(0xffffffffu, nid1, arr * 16 + row);
        cp16(sb1 + (uint32_t)(arr * 16 * ATW + row * ATW + d4 * 4) * 4,
             (const char*)g_aggr_h + ((size_t)(arr ? NN : 0) + j) * 128 + d4 * 16);
    }
    asm volatile("cp.async.commit_group;");

    float2 sc0 = __ldg(&g_scal[gnid0]);
    float2 sc1 = __ldg(&g_scal[gnid1]);
    float sii0 = (lane < 16) ? g_si[i0] : g_si[NN + i0];
    float sii1 = (lane < 16) ? g_si[i1] : g_si[NN + i1];

    asm volatile("cp.async.wait_group 1;" ::: "memory");   // node0 ready
    __syncwarp();
    attn_compute(sm[warp][0], sc0, sii0, i0, lane);

    asm volatile("cp.async.wait_group 0;" ::: "memory");   // node1 ready
    __syncwarp();
    attn_compute(sm[warp][1], sc1, sii1, i1, lane);
}

// ---------------- final weighted aggregate + sigmoid -> output ----------------
__global__ void out_kernel(const int* __restrict__ nbr1, const int* __restrict__ nbr2,
                           float* __restrict__ out) {
    int t = threadIdx.x;
    int nodeLocal = t >> 4;
    int q = t & 15;
    int node = blockIdx.x * 16 + nodeLocal;
    int g = node >= NN;
    int i = g ? node - NN : node;
    const int* nbr = g ? nbr2 : nbr1;
    size_t gbase = (size_t)g * NN;

    int nid = __ldg(&nbr[i * 16 + q]);
    float wq = g_norm[(size_t)node * 16 + q];

    float4 s = {0.f, 0.f, 0.f, 0.f};
#pragma unroll
    for (int k = 0; k < 16; k++) {
        int j = __shfl_sync(0xffffffffu, nid, k, 16);
        float w = __shfl_sync(0xffffffffu, wq, k, 16);
        uint2 raw = *(const uint2*)&g_yn_h[(gbase + j) * 64 + q * 4];
        float2 lo = __half22float2(*(__half2*)&raw.x);
        float2 hi = __half22float2(*(__half2*)&raw.y);
        s.x += w * lo.x; s.y += w * lo.y; s.z += w * hi.x; s.w += w * hi.y;
    }

    float4 ys = *(const float4*)&g_ys[(size_t)node * 64 + q * 4];
    float4 o0 = {sigmoidf_(ys.x), sigmoidf_(ys.y), sigmoidf_(ys.z), sigmoidf_(ys.w)};
    float4 o1 = {sigmoidf_(s.x), sigmoidf_(s.y), sigmoidf_(s.z), sigmoidf_(s.w)};
    *(float4*)&out[(size_t)node * 128 + q * 4] = o0;
    *(float4*)&out[(size_t)node * 128 + 64 + q * 4] = o1;
}

// ---------------- launch ----------------
extern "C" void kernel_launch(void* const* d_in, const int* in_sizes, int n_in,
                              void* d_out, int out_size) {
    const float* x1   = (const float*)d_in[0];
    const float* x2   = (const float*)d_in[1];
    const int*   nbr1 = (const int*)d_in[2];
    const int*   nbr2 = (const int*)d_in[3];
    const float* We1  = (const float*)d_in[4];
    const float* Ws1  = (const float*)d_in[5];
    const float* We2  = (const float*)d_in[6];
    const float* Ws2  = (const float*)d_in[7];
    const float* watt = (const float*)d_in[8];
    float* out = (float*)d_out;

    static cudaStream_t s_side = 0;
    static cudaEvent_t evF = 0, evJ = 0;
    static int smode = 0;
    if (smode == 0) {
        if (cudaStreamCreateWithFlags(&s_side, cudaStreamNonBlocking) == cudaSuccess &&
            cudaEventCreateWithFlags(&evF, cudaEventDisableTiming) == cudaSuccess &&
            cudaEventCreateWithFlags(&evJ, cudaEventDisableTiming) == cudaSuccess)
            smode = 1;
        else
            smode = -1;
    }

    cudaFuncSetAttribute(gemm_tc, cudaFuncAttributeMaxDynamicSharedMemorySize, GEMM_SMEM);

    pack_B_kernel<<<64, 256>>>(We1, Ws1, We2, Ws2);

    int gb = (2 * NN + 127) / 128;
    gemm_tc<<<gb, 256, GEMM_SMEM>>>(x1, x2, 1);

    aggr_kernel<<<(2 * NN) / 16, 256>>>(nbr1, nbr2, watt);

    if (smode == 1) {
        cudaEventRecord(evF, 0);
        cudaStreamWaitEvent(s_side, evF, 0);
        attn_kernel<<<NN / 8, 128, 0, s_side>>>(nbr1, nbr2);
        cudaEventRecord(evJ, s_side);
        gemm_tc<<<gb, 256, GEMM_SMEM>>>(x1, x2, 2);
        cudaStreamWaitEvent(0, evJ, 0);
    } else {
        attn_kernel<<<NN / 8, 128>>>(nbr1, nbr2);
        gemm_tc<<<gb, 256, GEMM_SMEM>>>(x1, x2, 2);
    }

    out_kernel<<<(2 * NN) / 16, 256>>>(nbr1, nbr2, out);
}

// round 13
// speedup vs baseline: 1.0352x; 1.0352x over previous
#include <cuda_runtime.h>
#include <cuda_fp16.h>
#include <cstdint>

#define NN 50000
#define KNBR 16

// ---------------- scratch (device globals; no runtime allocation) ----------------
__device__ __align__(16) __half g_B1h[128 * 128];     // [n][k] halves: W1 = [We1|Ws1]^T
__device__ __align__(16) __half g_B2h[128 * 128];     // [n][k] halves
__device__ __align__(16) float  g_zs[2 * NN * 64];    // xs (self transform), fp32
__device__ __align__(16) float  g_ys[2 * NN * 64];    // ys, fp32
__device__ __align__(16) __half g_zn_h[2 * NN * 64];  // xn fp16 (gather operand)
__device__ __align__(16) __half g_yn_h[2 * NN * 64];  // yn fp16 (gather operand)
__device__ __align__(16) __half g_h_h[2 * NN * 128];  // h = sigmoid(cat(xs,aggr)), fp16
__device__ __align__(16) __half g_aggr_h[2 * NN * 64];
__device__ __align__(8)  float2 g_scal[2 * NN];       // {nsq, sj} packed -> 1 LDG.64 gather
__device__ float g_si[2 * NN];
__device__ float g_norm[2 * NN * KNBR];

__device__ __forceinline__ float sigmoidf_(float x) { return 1.f / (1.f + __expf(-x)); }

__device__ __forceinline__ void mma_f16(float* d, const uint32_t* a, uint32_t b0, uint32_t b1) {
    asm volatile(
        "mma.sync.aligned.m16n8k16.row.col.f32.f16.f16.f32 "
        "{%0,%1,%2,%3}, {%4,%5,%6,%7}, {%8,%9}, {%0,%1,%2,%3};"
        : "+f"(d[0]), "+f"(d[1]), "+f"(d[2]), "+f"(d[3])
        : "r"(a[0]), "r"(a[1]), "r"(a[2]), "r"(a[3]), "r"(b0), "r"(b1));
}

__device__ __forceinline__ void ldm_x4(uint32_t* r, const uint32_t* p) {
    uint32_t addr = (uint32_t)__cvta_generic_to_shared(p);
    asm volatile("ldmatrix.sync.aligned.m8n8.x4.shared.b16 {%0,%1,%2,%3}, [%4];"
                 : "=r"(r[0]), "=r"(r[1]), "=r"(r[2]), "=r"(r[3]) : "r"(addr));
}

__device__ __forceinline__ void cp16(uint32_t smem_addr, const void* gptr) {
    asm volatile("cp.async.ca.shared.global [%0], [%1], 16;" :: "r"(smem_addr), "l"(gptr));
}

// ---------------- pack W -> [n][k] fp16 ----------------
__global__ void pack_B_kernel(const float* __restrict__ We1, const float* __restrict__ Ws1,
                              const float* __restrict__ We2, const float* __restrict__ Ws2) {
    int idx = blockIdx.x * blockDim.x + threadIdx.x;
    if (idx >= 128 * 128) return;
    int n = idx >> 7, k = idx & 127;
    float v1 = (n < 64) ? We1[k * 64 + n] : Ws1[k * 64 + (n - 64)];
    float v2 = (n < 64) ? We2[k * 64 + n] : Ws2[k * 64 + (n - 64)];
    g_B1h[idx] = __float2half_rn(v1);
    g_B2h[idx] = __float2half_rn(v2);
}

// ---------------- fp16 tensor-core GEMM: C[M,128] = A[M,128] @ B[128,128] ----------------
// Full K resident; 256 threads = 8 warps (4m x 2n); warp tile 32x64. (R8-frozen)
#define AG 68
#define GEMM_SMEM (2 * 128 * AG * 4)

__global__ void __launch_bounds__(256) gemm_tc(const float* __restrict__ x1,
                                               const float* __restrict__ x2, int layer) {
    extern __shared__ uint32_t smg[];
    uint32_t* As = smg;                 // [128 rows][AG words]
    uint32_t* Bs = smg + 128 * AG;      // [128 n][AG words]

    const int Mtot = 2 * NN;
    const __half* __restrict__ Bg = (layer == 1) ? g_B1h : g_B2h;
    float*  __restrict__ Cs = (layer == 1) ? g_zs : g_ys;
    __half* __restrict__ Ch = (layer == 1) ? g_zn_h : g_yn_h;

    int tid = threadIdx.x;
    int rowBase = blockIdx.x * 128;

    // ---- load A tile ----
    if (layer == 1) {
#pragma unroll
        for (int it = 0; it < 16; it++) {
            int row = (tid >> 5) + it * 8;
            int f4 = tid & 31;
            int grow = rowBase + row;
            float4 v = {0.f, 0.f, 0.f, 0.f};
            if (grow < Mtot) {
                const float* src = (grow < NN) ? (x1 + (size_t)grow * 128)
                                               : (x2 + (size_t)(grow - NN) * 128);
                v = *(const float4*)(src + f4 * 4);
            }
            __half2 w0 = __floats2half2_rn(v.x, v.y);
            __half2 w1 = __floats2half2_rn(v.z, v.w);
            uint2 w = {*(uint32_t*)&w0, *(uint32_t*)&w1};
            *(uint2*)&As[row * AG + f4 * 2] = w;
        }
    } else {
#pragma unroll
        for (int it = 0; it < 8; it++) {
            int row = (tid >> 4) + it * 16;
            int c = tid & 15;
            int grow = rowBase + row;
            uint4 v = {0, 0, 0, 0};
            if (grow < Mtot) v = *(const uint4*)&g_h_h[(size_t)grow * 128 + c * 8];
            *(uint4*)&As[row * AG + c * 4] = v;
        }
    }
    // ---- load B tile [n][k] ----
#pragma unroll
    for (int it = 0; it < 8; it++) {
        int n = (tid >> 4) + it * 16;
        int c = tid & 15;
        uint4 v = *(const uint4*)&Bg[(size_t)n * 128 + c * 8];
        *(uint4*)&Bs[n * AG + c * 4] = v;
    }
    __syncthreads();

    int lane = tid & 31;
    int wm = (tid >> 5) & 3;
    int wn = tid >> 7;
    int lr = lane & 7, lg = lane >> 3;

    float acc[2][8][4];
#pragma unroll
    for (int mf = 0; mf < 2; mf++)
#pragma unroll
        for (int nf = 0; nf < 8; nf++)
#pragma unroll
            for (int c = 0; c < 4; c++) acc[mf][nf][c] = 0.f;

#pragma unroll
    for (int ks = 0; ks < 8; ks++) {
        int kb = ks * 8;
        uint32_t a[2][4];
#pragma unroll
        for (int mf = 0; mf < 2; mf++) {
            int row = wm * 32 + mf * 16 + lr + (lg & 1) * 8;
            int word = kb + (lg >> 1) * 4;
            ldm_x4(a[mf], &As[row * AG + word]);
        }
        uint32_t b[8][2];
#pragma unroll
        for (int p = 0; p < 4; p++) {
            int n = wn * 64 + p * 16 + lr + (lg >> 1) * 8;
            int word = kb + (lg & 1) * 4;
            ldm_x4(&b[2 * p][0], &Bs[n * AG + word]);
        }
#pragma unroll
        for (int mf = 0; mf < 2; mf++)
#pragma unroll
            for (int nf = 0; nf < 8; nf++)
                mma_f16(acc[mf][nf], a[mf], b[nf][0], b[nf][1]);
    }

    // ---- epilogue: cols<64 -> fp16 (gather operand); cols>=64 -> fp32 self buffer ----
    int rq = lane >> 2, kq = lane & 3;
#pragma unroll
    for (int mf = 0; mf < 2; mf++) {
#pragma unroll
        for (int nf = 0; nf < 8; nf++) {
            int row = rowBase + wm * 32 + mf * 16 + rq;
            int col = nf * 8 + kq * 2;            // 0..63 within the wn half
            if (wn == 0) {
                if (row < Mtot) {
                    __half2 h = __floats2half2_rn(acc[mf][nf][0], acc[mf][nf][1]);
                    *(uint32_t*)&Ch[(size_t)row * 64 + col] = *(uint32_t*)&h;
                }
                if (row + 8 < Mtot) {
                    __half2 h = __floats2half2_rn(acc[mf][nf][2], acc[mf][nf][3]);
                    *(uint32_t*)&Ch[(size_t)(row + 8) * 64 + col] = *(uint32_t*)&h;
                }
            } else {
                if (row < Mtot) {
                    float2 v = {acc[mf][nf][0], acc[mf][nf][1]};
                    *(float2*)&Cs[(size_t)row * 64 + col] = v;
                }
                if (row + 8 < Mtot) {
                    float2 v = {acc[mf][nf][2], acc[mf][nf][3]};
                    *(float2*)&Cs[(size_t)(row + 8) * 64 + col] = v;
                }
            }
        }
    }
}

// ---------------- layer-1 aggregate + h + attention scalars ----------------
__global__ void aggr_kernel(const int* __restrict__ nbr1, const int* __restrict__ nbr2,
                            const float* __restrict__ watt) {
    int t = threadIdx.x;
    int nodeLocal = t >> 4;
    int q = t & 15;
    int node = blockIdx.x * 16 + nodeLocal;
    int g = node >= NN;
    int i = g ? node - NN : node;
    const int* nbr = g ? nbr2 : nbr1;
    size_t gbase = (size_t)g * NN;

    int nid = __ldg(&nbr[i * 16 + q]);

    float4 s = {0.f, 0.f, 0.f, 0.f};
#pragma unroll
    for (int k = 0; k < 16; k++) {
        int j = __shfl_sync(0xffffffffu, nid, k, 16);
        uint2 raw = *(const uint2*)&g_zn_h[(gbase + j) * 64 + q * 4];
        float2 lo = __half22float2(*(__half2*)&raw.x);
        float2 hi = __half22float2(*(__half2*)&raw.y);
        s.x += lo.x; s.y += lo.y; s.z += hi.x; s.w += hi.y;
    }
    s.x *= (1.f / 16.f); s.y *= (1.f / 16.f); s.z *= (1.f / 16.f); s.w *= (1.f / 16.f);

    __half2 h0 = __floats2half2_rn(s.x, s.y);
    __half2 h1 = __floats2half2_rn(s.z, s.w);
    uint2 packed = {*(uint32_t*)&h0, *(uint32_t*)&h1};
    *(uint2*)&g_aggr_h[(size_t)node * 64 + q * 4] = packed;
    float2 r0 = __half22float2(h0);
    float2 r1 = __half22float2(h1);

    float4 xs = *(const float4*)&g_zs[(size_t)node * 64 + q * 4];
    __half2 hx0 = __floats2half2_rn(sigmoidf_(xs.x), sigmoidf_(xs.y));
    __half2 hx1 = __floats2half2_rn(sigmoidf_(xs.z), sigmoidf_(xs.w));
    __half2 ha0 = __floats2half2_rn(sigmoidf_(s.x), sigmoidf_(s.y));
    __half2 ha1 = __floats2half2_rn(sigmoidf_(s.z), sigmoidf_(s.w));
    uint2 px = {*(uint32_t*)&hx0, *(uint32_t*)&hx1};
    uint2 pa = {*(uint32_t*)&ha0, *(uint32_t*)&ha1};
    *(uint2*)&g_h_h[(size_t)node * 128 + q * 4] = px;
    *(uint2*)&g_h_h[(size_t)node * 128 + 64 + q * 4] = pa;

    float4 w0 = *(const float4*)&watt[q * 4];
    float4 w1 = *(const float4*)&watt[64 + q * 4];
    float p0 = s.x * w0.x + s.y * w0.y + s.z * w0.z + s.w * w0.w;
    float p1 = s.x * w1.x + s.y * w1.y + s.z * w1.z + s.w * w1.w;
    float p2 = r0.x * r0.x + r0.y * r0.y + r1.x * r1.x + r1.y * r1.y;
#pragma unroll
    for (int o = 8; o; o >>= 1) {
        p0 += __shfl_xor_sync(0xffffffffu, p0, o);
        p1 += __shfl_xor_sync(0xffffffffu, p1, o);
        p2 += __shfl_xor_sync(0xffffffffu, p2, o);
    }
    if (q == 0) {
        g_si[node] = p0;
        g_scal[node] = make_float2(p2, p1);   // {nsq, sj}
    }
}

// ---------------- cross-attn + self-attn via f16 tensor-core Gram ----------------
#define ATW 36
__global__ void __launch_bounds__(128) attn_kernel(const int* __restrict__ nbr1,
                                                   const int* __restrict__ nbr2) {
    __shared__ uint32_t sm[4][2 * 16 * ATW];
    int warp = threadIdx.x >> 5;
    int lane = threadIdx.x & 31;
    int i = blockIdx.x * 4 + warp;
    uint32_t* a1s = sm[warp];
    uint32_t* a2s = sm[warp] + 16 * ATW;

    int nid;
    if (lane < 16) nid = nbr1[i * 16 + lane];
    else           nid = nbr2[i * 16 + (lane - 16)];
    int gnid = (lane < 16) ? nid : NN + nid;

    uint32_t sbase = (uint32_t)__cvta_generic_to_shared(sm[warp]);
#pragma unroll
    for (int it = 0; it < 8; it++) {
        int idx = it * 32 + lane;
        int arr = idx >> 7;
        int local = idx & 127;
        int row = local >> 3, d4 = local & 7;
        int j = __shfl_sync(0xffffffffu, nid, arr * 16 + row);
        cp16(sbase + (uint32_t)(arr * 16 * ATW + row * ATW + d4 * 4) * 4,
             (const char*)g_aggr_h + ((size_t)(arr ? NN : 0) + j) * 128 + d4 * 16);
    }
    asm volatile("cp.async.commit_group;");
    float2 sc = __ldg(&g_scal[gnid]);
    float myNsq = sc.x;
    asm volatile("cp.async.wait_group 0;" ::: "memory");
    __syncwarp();

    int rq = lane >> 2;
    int kq = lane & 3;
    int lr = lane & 7, lg = lane >> 3;
    float acc[2][4];
#pragma unroll
    for (int nt = 0; nt < 2; nt++)
#pragma unroll
        for (int c = 0; c < 4; c++) acc[nt][c] = 0.f;

#pragma unroll
    for (int ks = 0; ks < 4; ks++) {
        int kb = ks * 8;
        uint32_t a[4], b[2][2];
        ldm_x4(a, &a1s[(lr + (lg & 1) * 8) * ATW + kb + (lg >> 1) * 4]);
        ldm_x4(&b[0][0], &a2s[(lr + (lg >> 1) * 8) * ATW + kb + (lg & 1) * 4]);
        mma_f16(acc[0], a, b[0][0], b[0][1]);
        mma_f16(acc[1], a, b[1][0], b[1][1]);
    }

    float nsqK0 = __shfl_sync(0xffffffffu, myNsq, rq);
    float nsqK1 = __shfl_sync(0xffffffffu, myNsq, rq + 8);
    float rp0 = 0.f, rp1 = 0.f;
    float cp[2][2];
#pragma unroll
    for (int nt = 0; nt < 2; nt++) {
        float nsqL0 = __shfl_sync(0xffffffffu, myNsq, 16 + nt * 8 + 2 * kq);
        float nsqL1 = __shfl_sync(0xffffffffu, myNsq, 16 + nt * 8 + 2 * kq + 1);
        float s00 = __expf(-sqrtf(fmaxf(nsqK0 + nsqL0 - 2.f * acc[nt][0], 1e-12f)));
        float s01 = __expf(-sqrtf(fmaxf(nsqK0 + nsqL1 - 2.f * acc[nt][1], 1e-12f)));
        float s10 = __expf(-sqrtf(fmaxf(nsqK1 + nsqL0 - 2.f * acc[nt][2], 1e-12f)));
        float s11 = __expf(-sqrtf(fmaxf(nsqK1 + nsqL1 - 2.f * acc[nt][3], 1e-12f)));
        rp0 += s00 + s01;
        rp1 += s10 + s11;
        cp[nt][0] = s00 + s10;
        cp[nt][1] = s01 + s11;
    }

    rp0 += __shfl_xor_sync(0xffffffffu, rp0, 1);
    rp1 += __shfl_xor_sync(0xffffffffu, rp1, 1);
    rp0 += __shfl_xor_sync(0xffffffffu, rp0, 2);
    rp1 += __shfl_xor_sync(0xffffffffu, rp1, 2);
    float tot = rp0 + rp1;
#pragma unroll
    for (int o = 4; o <= 16; o <<= 1) tot += __shfl_xor_sync(0xffffffffu, tot, o);
#pragma unroll
    for (int o = 4; o <= 16; o <<= 1) {
        cp[0][0] += __shfl_xor_sync(0xffffffffu, cp[0][0], o);
        cp[0][1] += __shfl_xor_sync(0xffffffffu, cp[0][1], o);
        cp[1][0] += __shfl_xor_sync(0xffffffffu, cp[1][0], o);
        cp[1][1] += __shfl_xor_sync(0xffffffffu, cp[1][1], o);
    }

    int kl = lane & 15;
    float r0v = __shfl_sync(0xffffffffu, rp0, 4 * (kl & 7));
    float r1v = __shfl_sync(0xffffffffu, rp1, 4 * (kl & 7));
    float rowval = (kl < 8) ? r0v : r1v;
    int srcC = (kl & 7) >> 1;
    float c00 = __shfl_sync(0xffffffffu, cp[0][0], srcC);
    float c01 = __shfl_sync(0xffffffffu, cp[0][1], srcC);
    float c10 = __shfl_sync(0xffffffffu, cp[1][0], srcC);
    float c11 = __shfl_sync(0xffffffffu, cp[1][1], srcC);
    float colval = (kl >> 3) ? ((kl & 1) ? c11 : c10) : ((kl & 1) ? c01 : c00);

    float cross = __fdividef((lane < 16) ? rowval : colval, tot);

    float sii = (lane < 16) ? g_si[i] : g_si[NN + i];
    float sjv = sc.y;
    float zz = sii + sjv;
    float lr2 = (zz >= 0.f) ? zz : 0.01f * zz;
    float e = __expf(lr2);
    float esum = e;
#pragma unroll
    for (int o = 8; o; o >>= 1) esum += __shfl_xor_sync(0xffffffffu, esum, o);

    float nrm = cross * __fdividef(e, esum);
    if (lane < 16) g_norm[(size_t)i * 16 + lane] = nrm;
    else           g_norm[(size_t)(NN + i) * 16 + (lane - 16)] = nrm;
}

// ---------------- final weighted aggregate + sigmoid -> output ----------------
__global__ void out_kernel(const int* __restrict__ nbr1, const int* __restrict__ nbr2,
                           float* __restrict__ out) {
    int t = threadIdx.x;
    int nodeLocal = t >> 4;
    int q = t & 15;
    int node = blockIdx.x * 16 + nodeLocal;
    int g = node >= NN;
    int i = g ? node - NN : node;
    const int* nbr = g ? nbr2 : nbr1;
    size_t gbase = (size_t)g * NN;

    int nid = __ldg(&nbr[i * 16 + q]);
    float wq = g_norm[(size_t)node * 16 + q];

    float4 s = {0.f, 0.f, 0.f, 0.f};
#pragma unroll
    for (int k = 0; k < 16; k++) {
        int j = __shfl_sync(0xffffffffu, nid, k, 16);
        float w = __shfl_sync(0xffffffffu, wq, k, 16);
        uint2 raw = *(const uint2*)&g_yn_h[(gbase + j) * 64 + q * 4];
        float2 lo = __half22float2(*(__half2*)&raw.x);
        float2 hi = __half22float2(*(__half2*)&raw.y);
        s.x += w * lo.x; s.y += w * lo.y; s.z += w * hi.x; s.w += w * hi.y;
    }

    float4 ys = *(const float4*)&g_ys[(size_t)node * 64 + q * 4];
    float4 o0 = {sigmoidf_(ys.x), sigmoidf_(ys.y), sigmoidf_(ys.z), sigmoidf_(ys.w)};
    float4 o1 = {sigmoidf_(s.x), sigmoidf_(s.y), sigmoidf_(s.z), sigmoidf_(s.w)};
    *(float4*)&out[(size_t)node * 128 + q * 4] = o0;
    *(float4*)&out[(size_t)node * 128 + 64 + q * 4] = o1;
}

// ---------------- launch ----------------
extern "C" void kernel_launch(void* const* d_in, const int* in_sizes, int n_in,
                              void* d_out, int out_size) {
    const float* x1   = (const float*)d_in[0];
    const float* x2   = (const float*)d_in[1];
    const int*   nbr1 = (const int*)d_in[2];
    const int*   nbr2 = (const int*)d_in[3];
    const float* We1  = (const float*)d_in[4];
    const float* Ws1  = (const float*)d_in[5];
    const float* We2  = (const float*)d_in[6];
    const float* Ws2  = (const float*)d_in[7];
    const float* watt = (const float*)d_in[8];
    float* out = (float*)d_out;

    static cudaStream_t s_side = 0;
    static cudaEvent_t evF = 0, evJ = 0;
    static int smode = 0;
    if (smode == 0) {
        if (cudaStreamCreateWithFlags(&s_side, cudaStreamNonBlocking) == cudaSuccess &&
            cudaEventCreateWithFlags(&evF, cudaEventDisableTiming) == cudaSuccess &&
            cudaEventCreateWithFlags(&evJ, cudaEventDisableTiming) == cudaSuccess)
            smode = 1;
        else
            smode = -1;
    }

    cudaFuncSetAttribute(gemm_tc, cudaFuncAttributeMaxDynamicSharedMemorySize, GEMM_SMEM);

    pack_B_kernel<<<64, 256>>>(We1, Ws1, We2, Ws2);

    int gb = (2 * NN + 127) / 128;
    gemm_tc<<<gb, 256, GEMM_SMEM>>>(x1, x2, 1);

    aggr_kernel<<<(2 * NN) / 16, 256>>>(nbr1, nbr2, watt);

    if (smode == 1) {
        cudaEventRecord(evF, 0);
        cudaStreamWaitEvent(s_side, evF, 0);
        attn_kernel<<<NN / 4, 128, 0, s_side>>>(nbr1, nbr2);
        cudaEventRecord(evJ, s_side);
        gemm_tc<<<gb, 256, GEMM_SMEM>>>(x1, x2, 2);
        cudaStreamWaitEvent(0, evJ, 0);
    } else {
        attn_kernel<<<NN / 4, 128>>>(nbr1, nbr2);
        gemm_tc<<<gb, 256, GEMM_SMEM>>>(x1, x2, 2);
    }

    out_kernel<<<(2 * NN) / 16, 256>>>(nbr1, nbr2, out);
}

// round 14
// speedup vs baseline: 1.0537x; 1.0179x over previous
#include <cuda_runtime.h>
#include <cuda_fp16.h>
#include <cstdint>

#define NN 50000
#define KNBR 16

// ---------------- scratch (device globals; no runtime allocation) ----------------
__device__ __align__(16) __half g_B1h[128 * 128];     // [n][k] halves: W1 = [We1|Ws1]^T
__device__ __align__(16) __half g_B2h[128 * 128];     // [n][k] halves
__device__ __align__(16) float  g_zs[2 * NN * 64];    // xs (self transform), fp32
__device__ __align__(16) float  g_ys[2 * NN * 64];    // ys, fp32
__device__ __align__(16) __half g_zn_h[2 * NN * 64];  // xn fp16 (gather operand)
__device__ __align__(16) __half g_yn_h[2 * NN * 64];  // yn fp16 (gather operand)
__device__ __align__(16) __half g_h_h[2 * NN * 128];  // h = sigmoid(cat(xs,aggr)), fp16
__device__ __align__(16) __half g_aggr_h[2 * NN * 64];
__device__ __align__(8)  float2 g_scal[2 * NN];       // {nsq, sj} packed -> 1 LDG.64 gather
__device__ float g_si[2 * NN];
__device__ float g_norm[2 * NN * KNBR];

__device__ __forceinline__ float sigmoidf_(float x) { return 1.f / (1.f + __expf(-x)); }
// fast sqrt via MUFU.RSQ (x > 0 guaranteed by fmaxf clamp)
__device__ __forceinline__ float fsqrt_fast(float x) { return x * __frsqrt_rn(x); }

__device__ __forceinline__ void mma_f16(float* d, const uint32_t* a, uint32_t b0, uint32_t b1) {
    asm volatile(
        "mma.sync.aligned.m16n8k16.row.col.f32.f16.f16.f32 "
        "{%0,%1,%2,%3}, {%4,%5,%6,%7}, {%8,%9}, {%0,%1,%2,%3};"
        : "+f"(d[0]), "+f"(d[1]), "+f"(d[2]), "+f"(d[3])
        : "r"(a[0]), "r"(a[1]), "r"(a[2]), "r"(a[3]), "r"(b0), "r"(b1));
}

__device__ __forceinline__ void ldm_x4(uint32_t* r, const uint32_t* p) {
    uint32_t addr = (uint32_t)__cvta_generic_to_shared(p);
    asm volatile("ldmatrix.sync.aligned.m8n8.x4.shared.b16 {%0,%1,%2,%3}, [%4];"
                 : "=r"(r[0]), "=r"(r[1]), "=r"(r[2]), "=r"(r[3]) : "r"(addr));
}

// L2-direct async copy (single-use random rows: skip L1 allocation)
__device__ __forceinline__ void cp16(uint32_t smem_addr, const void* gptr) {
    asm volatile("cp.async.cg.shared.global [%0], [%1], 16;" :: "r"(smem_addr), "l"(gptr));
}

// ---------------- pack W -> [n][k] fp16 ----------------
__global__ void pack_B_kernel(const float* __restrict__ We1, const float* __restrict__ Ws1,
                              const float* __restrict__ We2, const float* __restrict__ Ws2) {
    int idx = blockIdx.x * blockDim.x + threadIdx.x;
    if (idx >= 128 * 128) return;
    int n = idx >> 7, k = idx & 127;
    float v1 = (n < 64) ? We1[k * 64 + n] : Ws1[k * 64 + (n - 64)];
    float v2 = (n < 64) ? We2[k * 64 + n] : Ws2[k * 64 + (n - 64)];
    g_B1h[idx] = __float2half_rn(v1);
    g_B2h[idx] = __float2half_rn(v2);
}

// ---------------- fp16 tensor-core GEMM: C[M,128] = A[M,128] @ B[128,128] ----------------
// Full K resident; 256 threads = 8 warps (4m x 2n); warp tile 32x64. (R8-frozen)
#define AG 68
#define GEMM_SMEM (2 * 128 * AG * 4)

__global__ void __launch_bounds__(256) gemm_tc(const float* __restrict__ x1,
                                               const float* __restrict__ x2, int layer) {
    extern __shared__ uint32_t smg[];
    uint32_t* As = smg;                 // [128 rows][AG words]
    uint32_t* Bs = smg + 128 * AG;      // [128 n][AG words]

    const int Mtot = 2 * NN;
    const __half* __restrict__ Bg = (layer == 1) ? g_B1h : g_B2h;
    float*  __restrict__ Cs = (layer == 1) ? g_zs : g_ys;
    __half* __restrict__ Ch = (layer == 1) ? g_zn_h : g_yn_h;

    int tid = threadIdx.x;
    int rowBase = blockIdx.x * 128;

    // ---- load A tile ----
    if (layer == 1) {
#pragma unroll
        for (int it = 0; it < 16; it++) {
            int row = (tid >> 5) + it * 8;
            int f4 = tid & 31;
            int grow = rowBase + row;
            float4 v = {0.f, 0.f, 0.f, 0.f};
            if (grow < Mtot) {
                const float* src = (grow < NN) ? (x1 + (size_t)grow * 128)
                                               : (x2 + (size_t)(grow - NN) * 128);
                v = *(const float4*)(src + f4 * 4);
            }
            __half2 w0 = __floats2half2_rn(v.x, v.y);
            __half2 w1 = __floats2half2_rn(v.z, v.w);
            uint2 w = {*(uint32_t*)&w0, *(uint32_t*)&w1};
            *(uint2*)&As[row * AG + f4 * 2] = w;
        }
    } else {
#pragma unroll
        for (int it = 0; it < 8; it++) {
            int row = (tid >> 4) + it * 16;
            int c = tid & 15;
            int grow = rowBase + row;
            uint4 v = {0, 0, 0, 0};
            if (grow < Mtot) v = *(const uint4*)&g_h_h[(size_t)grow * 128 + c * 8];
            *(uint4*)&As[row * AG + c * 4] = v;
        }
    }
    // ---- load B tile [n][k] ----
#pragma unroll
    for (int it = 0; it < 8; it++) {
        int n = (tid >> 4) + it * 16;
        int c = tid & 15;
        uint4 v = *(const uint4*)&Bg[(size_t)n * 128 + c * 8];
        *(uint4*)&Bs[n * AG + c * 4] = v;
    }
    __syncthreads();

    int lane = tid & 31;
    int wm = (tid >> 5) & 3;
    int wn = tid >> 7;
    int lr = lane & 7, lg = lane >> 3;

    float acc[2][8][4];
#pragma unroll
    for (int mf = 0; mf < 2; mf++)
#pragma unroll
        for (int nf = 0; nf < 8; nf++)
#pragma unroll
            for (int c = 0; c < 4; c++) acc[mf][nf][c] = 0.f;

#pragma unroll
    for (int ks = 0; ks < 8; ks++) {
        int kb = ks * 8;
        uint32_t a[2][4];
#pragma unroll
        for (int mf = 0; mf < 2; mf++) {
            int row = wm * 32 + mf * 16 + lr + (lg & 1) * 8;
            int word = kb + (lg >> 1) * 4;
            ldm_x4(a[mf], &As[row * AG + word]);
        }
        uint32_t b[8][2];
#pragma unroll
        for (int p = 0; p < 4; p++) {
            int n = wn * 64 + p * 16 + lr + (lg >> 1) * 8;
            int word = kb + (lg & 1) * 4;
            ldm_x4(&b[2 * p][0], &Bs[n * AG + word]);
        }
#pragma unroll
        for (int mf = 0; mf < 2; mf++)
#pragma unroll
            for (int nf = 0; nf < 8; nf++)
                mma_f16(acc[mf][nf], a[mf], b[nf][0], b[nf][1]);
    }

    // ---- epilogue: cols<64 -> fp16 (gather operand); cols>=64 -> fp32 self buffer ----
    int rq = lane >> 2, kq = lane & 3;
#pragma unroll
    for (int mf = 0; mf < 2; mf++) {
#pragma unroll
        for (int nf = 0; nf < 8; nf++) {
            int row = rowBase + wm * 32 + mf * 16 + rq;
            int col = nf * 8 + kq * 2;            // 0..63 within the wn half
            if (wn == 0) {
                if (row < Mtot) {
                    __half2 h = __floats2half2_rn(acc[mf][nf][0], acc[mf][nf][1]);
                    *(uint32_t*)&Ch[(size_t)row * 64 + col] = *(uint32_t*)&h;
                }
                if (row + 8 < Mtot) {
                    __half2 h = __floats2half2_rn(acc[mf][nf][2], acc[mf][nf][3]);
                    *(uint32_t*)&Ch[(size_t)(row + 8) * 64 + col] = *(uint32_t*)&h;
                }
            } else {
                if (row < Mtot) {
                    float2 v = {acc[mf][nf][0], acc[mf][nf][1]};
                    *(float2*)&Cs[(size_t)row * 64 + col] = v;
                }
                if (row + 8 < Mtot) {
                    float2 v = {acc[mf][nf][2], acc[mf][nf][3]};
                    *(float2*)&Cs[(size_t)(row + 8) * 64 + col] = v;
                }
            }
        }
    }
}

// ---------------- layer-1 aggregate + h + attention scalars ----------------
__global__ void aggr_kernel(const int* __restrict__ nbr1, const int* __restrict__ nbr2,
                            const float* __restrict__ watt) {
    int t = threadIdx.x;
    int nodeLocal = t >> 4;
    int q = t & 15;
    int node = blockIdx.x * 16 + nodeLocal;
    int g = node >= NN;
    int i = g ? node - NN : node;
    const int* nbr = g ? nbr2 : nbr1;
    size_t gbase = (size_t)g * NN;

    int nid = __ldg(&nbr[i * 16 + q]);

    float4 s = {0.f, 0.f, 0.f, 0.f};
#pragma unroll
    for (int k = 0; k < 16; k++) {
        int j = __shfl_sync(0xffffffffu, nid, k, 16);
        uint2 raw = __ldcg((const uint2*)&g_zn_h[(gbase + j) * 64 + q * 4]);
        float2 lo = __half22float2(*(__half2*)&raw.x);
        float2 hi = __half22float2(*(__half2*)&raw.y);
        s.x += lo.x; s.y += lo.y; s.z += hi.x; s.w += hi.y;
    }
    s.x *= (1.f / 16.f); s.y *= (1.f / 16.f); s.z *= (1.f / 16.f); s.w *= (1.f / 16.f);

    __half2 h0 = __floats2half2_rn(s.x, s.y);
    __half2 h1 = __floats2half2_rn(s.z, s.w);
    uint2 packed = {*(uint32_t*)&h0, *(uint32_t*)&h1};
    *(uint2*)&g_aggr_h[(size_t)node * 64 + q * 4] = packed;
    float2 r0 = __half22float2(h0);
    float2 r1 = __half22float2(h1);

    float4 xs = *(const float4*)&g_zs[(size_t)node * 64 + q * 4];
    __half2 hx0 = __floats2half2_rn(sigmoidf_(xs.x), sigmoidf_(xs.y));
    __half2 hx1 = __floats2half2_rn(sigmoidf_(xs.z), sigmoidf_(xs.w));
    __half2 ha0 = __floats2half2_rn(sigmoidf_(s.x), sigmoidf_(s.y));
    __half2 ha1 = __floats2half2_rn(sigmoidf_(s.z), sigmoidf_(s.w));
    uint2 px = {*(uint32_t*)&hx0, *(uint32_t*)&hx1};
    uint2 pa = {*(uint32_t*)&ha0, *(uint32_t*)&ha1};
    *(uint2*)&g_h_h[(size_t)node * 128 + q * 4] = px;
    *(uint2*)&g_h_h[(size_t)node * 128 + 64 + q * 4] = pa;

    float4 w0 = *(const float4*)&watt[q * 4];
    float4 w1 = *(const float4*)&watt[64 + q * 4];
    float p0 = s.x * w0.x + s.y * w0.y + s.z * w0.z + s.w * w0.w;
    float p1 = s.x * w1.x + s.y * w1.y + s.z * w1.z + s.w * w1.w;
    float p2 = r0.x * r0.x + r0.y * r0.y + r1.x * r1.x + r1.y * r1.y;
#pragma unroll
    for (int o = 8; o; o >>= 1) {
        p0 += __shfl_xor_sync(0xffffffffu, p0, o);
        p1 += __shfl_xor_sync(0xffffffffu, p1, o);
        p2 += __shfl_xor_sync(0xffffffffu, p2, o);
    }
    if (q == 0) {
        g_si[node] = p0;
        g_scal[node] = make_float2(p2, p1);   // {nsq, sj}
    }
}

// ---------------- cross-attn + self-attn via f16 tensor-core Gram ----------------
#define ATW 36
__global__ void __launch_bounds__(128) attn_kernel(const int* __restrict__ nbr1,
                                                   const int* __restrict__ nbr2) {
    __shared__ uint32_t sm[4][2 * 16 * ATW];
    int warp = threadIdx.x >> 5;
    int lane = threadIdx.x & 31;
    int i = blockIdx.x * 4 + warp;
    uint32_t* a1s = sm[warp];
    uint32_t* a2s = sm[warp] + 16 * ATW;

    int nid;
    if (lane < 16) nid = nbr1[i * 16 + lane];
    else           nid = nbr2[i * 16 + (lane - 16)];
    int gnid = (lane < 16) ? nid : NN + nid;

    uint32_t sbase = (uint32_t)__cvta_generic_to_shared(sm[warp]);
#pragma unroll
    for (int it = 0; it < 8; it++) {
        int idx = it * 32 + lane;
        int arr = idx >> 7;
        int local = idx & 127;
        int row = local >> 3, d4 = local & 7;
        int j = __shfl_sync(0xffffffffu, nid, arr * 16 + row);
        cp16(sbase + (uint32_t)(arr * 16 * ATW + row * ATW + d4 * 4) * 4,
             (const char*)g_aggr_h + ((size_t)(arr ? NN : 0) + j) * 128 + d4 * 16);
    }
    asm volatile("cp.async.commit_group;");
    float2 sc = __ldg(&g_scal[gnid]);
    float myNsq = sc.x;
    asm volatile("cp.async.wait_group 0;" ::: "memory");
    __syncwarp();

    int rq = lane >> 2;
    int kq = lane & 3;
    int lr = lane & 7, lg = lane >> 3;
    float acc[2][4];
#pragma unroll
    for (int nt = 0; nt < 2; nt++)
#pragma unroll
        for (int c = 0; c < 4; c++) acc[nt][c] = 0.f;

#pragma unroll
    for (int ks = 0; ks < 4; ks++) {
        int kb = ks * 8;
        uint32_t a[4], b[2][2];
        ldm_x4(a, &a1s[(lr + (lg & 1) * 8) * ATW + kb + (lg >> 1) * 4]);
        ldm_x4(&b[0][0], &a2s[(lr + (lg >> 1) * 8) * ATW + kb + (lg & 1) * 4]);
        mma_f16(acc[0], a, b[0][0], b[0][1]);
        mma_f16(acc[1], a, b[1][0], b[1][1]);
    }

    float nsqK0 = __shfl_sync(0xffffffffu, myNsq, rq);
    float nsqK1 = __shfl_sync(0xffffffffu, myNsq, rq + 8);
    float rp0 = 0.f, rp1 = 0.f;
    float cp[2][2];
#pragma unroll
    for (int nt = 0; nt < 2; nt++) {
        float nsqL0 = __shfl_sync(0xffffffffu, myNsq, 16 + nt * 8 + 2 * kq);
        float nsqL1 = __shfl_sync(0xffffffffu, myNsq, 16 + nt * 8 + 2 * kq + 1);
        float d00 = fmaxf(nsqK0 + nsqL0 - 2.f * acc[nt][0], 1e-12f);
        float d01 = fmaxf(nsqK0 + nsqL1 - 2.f * acc[nt][1], 1e-12f);
        float d10 = fmaxf(nsqK1 + nsqL0 - 2.f * acc[nt][2], 1e-12f);
        float d11 = fmaxf(nsqK1 + nsqL1 - 2.f * acc[nt][3], 1e-12f);
        float s00 = __expf(-fsqrt_fast(d00));
        float s01 = __expf(-fsqrt_fast(d01));
        float s10 = __expf(-fsqrt_fast(d10));
        float s11 = __expf(-fsqrt_fast(d11));
        rp0 += s00 + s01;
        rp1 += s10 + s11;
        cp[nt][0] = s00 + s10;
        cp[nt][1] = s01 + s11;
    }

    rp0 += __shfl_xor_sync(0xffffffffu, rp0, 1);
    rp1 += __shfl_xor_sync(0xffffffffu, rp1, 1);
    rp0 += __shfl_xor_sync(0xffffffffu, rp0, 2);
    rp1 += __shfl_xor_sync(0xffffffffu, rp1, 2);
    float tot = rp0 + rp1;
#pragma unroll
    for (int o = 4; o <= 16; o <<= 1) tot += __shfl_xor_sync(0xffffffffu, tot, o);
#pragma unroll
    for (int o = 4; o <= 16; o <<= 1) {
        cp[0][0] += __shfl_xor_sync(0xffffffffu, cp[0][0], o);
        cp[0][1] += __shfl_xor_sync(0xffffffffu, cp[0][1], o);
        cp[1][0] += __shfl_xor_sync(0xffffffffu, cp[1][0], o);
        cp[1][1] += __shfl_xor_sync(0xffffffffu, cp[1][1], o);
    }

    int kl = lane & 15;
    float r0v = __shfl_sync(0xffffffffu, rp0, 4 * (kl & 7));
    float r1v = __shfl_sync(0xffffffffu, rp1, 4 * (kl & 7));
    float rowval = (kl < 8) ? r0v : r1v;
    int srcC = (kl & 7) >> 1;
    float c00 = __shfl_sync(0xffffffffu, cp[0][0], srcC);
    float c01 = __shfl_sync(0xffffffffu, cp[0][1], srcC);
    float c10 = __shfl_sync(0xffffffffu, cp[1][0], srcC);
    float c11 = __shfl_sync(0xffffffffu, cp[1][1], srcC);
    float colval = (kl >> 3) ? ((kl & 1) ? c11 : c10) : ((kl & 1) ? c01 : c00);

    float cross = __fdividef((lane < 16) ? rowval : colval, tot);

    float sii = (lane < 16) ? g_si[i] : g_si[NN + i];
    float sjv = sc.y;
    float zz = sii + sjv;
    float lr2 = (zz >= 0.f) ? zz : 0.01f * zz;
    float e = __expf(lr2);
    float esum = e;
#pragma unroll
    for (int o = 8; o; o >>= 1) esum += __shfl_xor_sync(0xffffffffu, esum, o);

    float nrm = cross * __fdividef(e, esum);
    if (lane < 16) g_norm[(size_t)i * 16 + lane] = nrm;
    else           g_norm[(size_t)(NN + i) * 16 + (lane - 16)] = nrm;
}

// ---------------- final weighted aggregate + sigmoid -> output ----------------
__global__ void out_kernel(const int* __restrict__ nbr1, const int* __restrict__ nbr2,
                           float* __restrict__ out) {
    int t = threadIdx.x;
    int nodeLocal = t >> 4;
    int q = t & 15;
    int node = blockIdx.x * 16 + nodeLocal;
    int g = node >= NN;
    int i = g ? node - NN : node;
    const int* nbr = g ? nbr2 : nbr1;
    size_t gbase = (size_t)g * NN;

    int nid = __ldg(&nbr[i * 16 + q]);
    float wq = g_norm[(size_t)node * 16 + q];

    float4 s = {0.f, 0.f, 0.f, 0.f};
#pragma unroll
    for (int k = 0; k < 16; k++) {
        int j = __shfl_sync(0xffffffffu, nid, k, 16);
        float w = __shfl_sync(0xffffffffu, wq, k, 16);
        uint2 raw = __ldcg((const uint2*)&g_yn_h[(gbase + j) * 64 + q * 4]);
        float2 lo = __half22float2(*(__half2*)&raw.x);
        float2 hi = __half22float2(*(__half2*)&raw.y);
        s.x += w * lo.x; s.y += w * lo.y; s.z += w * hi.x; s.w += w * hi.y;
    }

    float4 ys = *(const float4*)&g_ys[(size_t)node * 64 + q * 4];
    float4 o0 = {sigmoidf_(ys.x), sigmoidf_(ys.y), sigmoidf_(ys.z), sigmoidf_(ys.w)};
    float4 o1 = {sigmoidf_(s.x), sigmoidf_(s.y), sigmoidf_(s.z), sigmoidf_(s.w)};
    *(float4*)&out[(size_t)node * 128 + q * 4] = o0;
    *(float4*)&out[(size_t)node * 128 + 64 + q * 4] = o1;
}

// ---------------- launch ----------------
extern "C" void kernel_launch(void* const* d_in, const int* in_sizes, int n_in,
                              void* d_out, int out_size) {
    const float* x1   = (const float*)d_in[0];
    const float* x2   = (const float*)d_in[1];
    const int*   nbr1 = (const int*)d_in[2];
    const int*   nbr2 = (const int*)d_in[3];
    const float* We1  = (const float*)d_in[4];
    const float* Ws1  = (const float*)d_in[5];
    const float* We2  = (const float*)d_in[6];
    const float* Ws2  = (const float*)d_in[7];
    const float* watt = (const float*)d_in[8];
    float* out = (float*)d_out;

    static cudaStream_t s_side = 0;
    static cudaEvent_t evF = 0, evJ = 0;
    static int smode = 0;
    if (smode == 0) {
        if (cudaStreamCreateWithFlags(&s_side, cudaStreamNonBlocking) == cudaSuccess &&
            cudaEventCreateWithFlags(&evF, cudaEventDisableTiming) == cudaSuccess &&
            cudaEventCreateWithFlags(&evJ, cudaEventDisableTiming) == cudaSuccess)
            smode = 1;
        else
            smode = -1;
    }

    cudaFuncSetAttribute(gemm_tc, cudaFuncAttributeMaxDynamicSharedMemorySize, GEMM_SMEM);

    pack_B_kernel<<<64, 256>>>(We1, Ws1, We2, Ws2);

    int gb = (2 * NN + 127) / 128;
    gemm_tc<<<gb, 256, GEMM_SMEM>>>(x1, x2, 1);

    aggr_kernel<<<(2 * NN) / 16, 256>>>(nbr1, nbr2, watt);

    if (smode == 1) {
        cudaEventRecord(evF, 0);
        cudaStreamWaitEvent(s_side, evF, 0);
        attn_kernel<<<NN / 4, 128, 0, s_side>>>(nbr1, nbr2);
        cudaEventRecord(evJ, s_side);
        gemm_tc<<<gb, 256, GEMM_SMEM>>>(x1, x2, 2);
        cudaStreamWaitEvent(0, evJ, 0);
    } else {
        attn_kernel<<<NN / 4, 128>>>(nbr1, nbr2);
        gemm_tc<<<gb, 256, GEMM_SMEM>>>(x1, x2, 2);
    }

    out_kernel<<<(2 * NN) / 16, 256>>>(nbr1, nbr2, out);
}

// round 15
// speedup vs baseline: 1.0604x; 1.0063x over previous
#include <cuda_runtime.h>
#include <cuda_fp16.h>
#include <cstdint>

#define NN 50000
#define KNBR 16

// ---------------- scratch (device globals; no runtime allocation) ----------------
__device__ __align__(16) __half g_B1h[128 * 128];     // [n][k] halves: W1 = [We1|Ws1]^T
__device__ __align__(16) __half g_B2h[128 * 128];     // [n][k] halves
__device__ __align__(16) float  g_zs[2 * NN * 64];    // xs (self transform), fp32
__device__ __align__(16) float  g_ys[2 * NN * 64];    // ys, fp32
__device__ __align__(16) __half g_zn_h[2 * NN * 64];  // xn fp16 (gather operand)
__device__ __align__(16) __half g_yn_h[2 * NN * 64];  // yn fp16 (gather operand)
__device__ __align__(16) __half g_h_h[2 * NN * 128];  // h = sigmoid(cat(xs,aggr)), fp16
__device__ __align__(16) __half g_aggr_h[2 * NN * 64];
__device__ __align__(8)  float2 g_scal[2 * NN];       // {nsq, sj} packed -> 1 LDG.64 gather
__device__ float g_si[2 * NN];
__device__ float g_norm[2 * NN * KNBR];

__device__ __forceinline__ float sigmoidf_(float x) { return 1.f / (1.f + __expf(-x)); }
// fast sqrt via MUFU.RSQ (x > 0 guaranteed by fmaxf clamp)
__device__ __forceinline__ float fsqrt_fast(float x) { return x * __frsqrt_rn(x); }

__device__ __forceinline__ void mma_f16(float* d, const uint32_t* a, uint32_t b0, uint32_t b1) {
    asm volatile(
        "mma.sync.aligned.m16n8k16.row.col.f32.f16.f16.f32 "
        "{%0,%1,%2,%3}, {%4,%5,%6,%7}, {%8,%9}, {%0,%1,%2,%3};"
        : "+f"(d[0]), "+f"(d[1]), "+f"(d[2]), "+f"(d[3])
        : "r"(a[0]), "r"(a[1]), "r"(a[2]), "r"(a[3]), "r"(b0), "r"(b1));
}

__device__ __forceinline__ void ldm_x4(uint32_t* r, const uint32_t* p) {
    uint32_t addr = (uint32_t)__cvta_generic_to_shared(p);
    asm volatile("ldmatrix.sync.aligned.m8n8.x4.shared.b16 {%0,%1,%2,%3}, [%4];"
                 : "=r"(r[0]), "=r"(r[1]), "=r"(r[2]), "=r"(r[3]) : "r"(addr));
}

// L2-direct async copy (single-use random rows: skip L1 allocation)
__device__ __forceinline__ void cp16(uint32_t smem_addr, const void* gptr) {
    asm volatile("cp.async.cg.shared.global [%0], [%1], 16;" :: "r"(smem_addr), "l"(gptr));
}

// ---------------- pack W -> [n][k] fp16 ----------------
__global__ void pack_B_kernel(const float* __restrict__ We1, const float* __restrict__ Ws1,
                              const float* __restrict__ We2, const float* __restrict__ Ws2) {
    int idx = blockIdx.x * blockDim.x + threadIdx.x;
    if (idx >= 128 * 128) return;
    int n = idx >> 7, k = idx & 127;
    float v1 = (n < 64) ? We1[k * 64 + n] : Ws1[k * 64 + (n - 64)];
    float v2 = (n < 64) ? We2[k * 64 + n] : Ws2[k * 64 + (n - 64)];
    g_B1h[idx] = __float2half_rn(v1);
    g_B2h[idx] = __float2half_rn(v2);
}

// ---------------- fp16 tensor-core GEMM: C[M,128] = A[M,128] @ B[128,128] ----------------
// Full K resident; 256 threads = 8 warps (4m x 2n); warp tile 32x64. (R8-frozen structure)
#define AG 68
#define GEMM_SMEM (2 * 128 * AG * 4)

__global__ void __launch_bounds__(256) gemm_tc(const float* __restrict__ x1,
                                               const float* __restrict__ x2, int layer) {
    extern __shared__ uint32_t smg[];
    uint32_t* As = smg;                 // [128 rows][AG words]
    uint32_t* Bs = smg + 128 * AG;      // [128 n][AG words]

    const int Mtot = 2 * NN;
    const __half* __restrict__ Bg = (layer == 1) ? g_B1h : g_B2h;
    float*  __restrict__ Cs = (layer == 1) ? g_zs : g_ys;
    __half* __restrict__ Ch = (layer == 1) ? g_zn_h : g_yn_h;

    int tid = threadIdx.x;
    int rowBase = blockIdx.x * 128;

    // ---- load A tile (single-use stream -> L2-direct) ----
    if (layer == 1) {
#pragma unroll
        for (int it = 0; it < 16; it++) {
            int row = (tid >> 5) + it * 8;
            int f4 = tid & 31;
            int grow = rowBase + row;
            float4 v = {0.f, 0.f, 0.f, 0.f};
            if (grow < Mtot) {
                const float4* src = (grow < NN)
                    ? (const float4*)(x1 + (size_t)grow * 128)
                    : (const float4*)(x2 + (size_t)(grow - NN) * 128);
                v = __ldcg(src + f4);
            }
            __half2 w0 = __floats2half2_rn(v.x, v.y);
            __half2 w1 = __floats2half2_rn(v.z, v.w);
            uint2 w = {*(uint32_t*)&w0, *(uint32_t*)&w1};
            *(uint2*)&As[row * AG + f4 * 2] = w;
        }
    } else {
#pragma unroll
        for (int it = 0; it < 8; it++) {
            int row = (tid >> 4) + it * 16;
            int c = tid & 15;
            int grow = rowBase + row;
            uint4 v = {0, 0, 0, 0};
            if (grow < Mtot) v = __ldcg((const uint4*)&g_h_h[(size_t)grow * 128 + c * 8]);
            *(uint4*)&As[row * AG + c * 4] = v;
        }
    }
    // ---- load B tile [n][k] (reused across blocks: keep default cached path) ----
#pragma unroll
    for (int it = 0; it < 8; it++) {
        int n = (tid >> 4) + it * 16;
        int c = tid & 15;
        uint4 v = *(const uint4*)&Bg[(size_t)n * 128 + c * 8];
        *(uint4*)&Bs[n * AG + c * 4] = v;
    }
    __syncthreads();

    int lane = tid & 31;
    int wm = (tid >> 5) & 3;
    int wn = tid >> 7;
    int lr = lane & 7, lg = lane >> 3;

    float acc[2][8][4];
#pragma unroll
    for (int mf = 0; mf < 2; mf++)
#pragma unroll
        for (int nf = 0; nf < 8; nf++)
#pragma unroll
            for (int c = 0; c < 4; c++) acc[mf][nf][c] = 0.f;

#pragma unroll
    for (int ks = 0; ks < 8; ks++) {
        int kb = ks * 8;
        uint32_t a[2][4];
#pragma unroll
        for (int mf = 0; mf < 2; mf++) {
            int row = wm * 32 + mf * 16 + lr + (lg & 1) * 8;
            int word = kb + (lg >> 1) * 4;
            ldm_x4(a[mf], &As[row * AG + word]);
        }
        uint32_t b[8][2];
#pragma unroll
        for (int p = 0; p < 4; p++) {
            int n = wn * 64 + p * 16 + lr + (lg >> 1) * 8;
            int word = kb + (lg & 1) * 4;
            ldm_x4(&b[2 * p][0], &Bs[n * AG + word]);
        }
#pragma unroll
        for (int mf = 0; mf < 2; mf++)
#pragma unroll
            for (int nf = 0; nf < 8; nf++)
                mma_f16(acc[mf][nf], a[mf], b[nf][0], b[nf][1]);
    }

    // ---- epilogue: cols<64 -> fp16 (gather operand); cols>=64 -> fp32 self buffer ----
    int rq = lane >> 2, kq = lane & 3;
#pragma unroll
    for (int mf = 0; mf < 2; mf++) {
#pragma unroll
        for (int nf = 0; nf < 8; nf++) {
            int row = rowBase + wm * 32 + mf * 16 + rq;
            int col = nf * 8 + kq * 2;            // 0..63 within the wn half
            if (wn == 0) {
                if (row < Mtot) {
                    __half2 h = __floats2half2_rn(acc[mf][nf][0], acc[mf][nf][1]);
                    *(uint32_t*)&Ch[(size_t)row * 64 + col] = *(uint32_t*)&h;
                }
                if (row + 8 < Mtot) {
                    __half2 h = __floats2half2_rn(acc[mf][nf][2], acc[mf][nf][3]);
                    *(uint32_t*)&Ch[(size_t)(row + 8) * 64 + col] = *(uint32_t*)&h;
                }
            } else {
                if (row < Mtot) {
                    float2 v = {acc[mf][nf][0], acc[mf][nf][1]};
                    *(float2*)&Cs[(size_t)row * 64 + col] = v;
                }
                if (row + 8 < Mtot) {
                    float2 v = {acc[mf][nf][2], acc[mf][nf][3]};
                    *(float2*)&Cs[(size_t)(row + 8) * 64 + col] = v;
                }
            }
        }
    }
}

// ---------------- layer-1 aggregate + h + attention scalars ----------------
__global__ void aggr_kernel(const int* __restrict__ nbr1, const int* __restrict__ nbr2,
                            const float* __restrict__ watt) {
    int t = threadIdx.x;
    int nodeLocal = t >> 4;
    int q = t & 15;
    int node = blockIdx.x * 16 + nodeLocal;
    int g = node >= NN;
    int i = g ? node - NN : node;
    const int* nbr = g ? nbr2 : nbr1;
    size_t gbase = (size_t)g * NN;

    int nid = __ldg(&nbr[i * 16 + q]);

    float4 s = {0.f, 0.f, 0.f, 0.f};
#pragma unroll
    for (int k = 0; k < 16; k++) {
        int j = __shfl_sync(0xffffffffu, nid, k, 16);
        uint2 raw = __ldcg((const uint2*)&g_zn_h[(gbase + j) * 64 + q * 4]);
        float2 lo = __half22float2(*(__half2*)&raw.x);
        float2 hi = __half22float2(*(__half2*)&raw.y);
        s.x += lo.x; s.y += lo.y; s.z += hi.x; s.w += hi.y;
    }
    s.x *= (1.f / 16.f); s.y *= (1.f / 16.f); s.z *= (1.f / 16.f); s.w *= (1.f / 16.f);

    __half2 h0 = __floats2half2_rn(s.x, s.y);
    __half2 h1 = __floats2half2_rn(s.z, s.w);
    uint2 packed = {*(uint32_t*)&h0, *(uint32_t*)&h1};
    *(uint2*)&g_aggr_h[(size_t)node * 64 + q * 4] = packed;
    float2 r0 = __half22float2(h0);
    float2 r1 = __half22float2(h1);

    float4 xs = __ldcg((const float4*)&g_zs[(size_t)node * 64 + q * 4]);
    __half2 hx0 = __floats2half2_rn(sigmoidf_(xs.x), sigmoidf_(xs.y));
    __half2 hx1 = __floats2half2_rn(sigmoidf_(xs.z), sigmoidf_(xs.w));
    __half2 ha0 = __floats2half2_rn(sigmoidf_(s.x), sigmoidf_(s.y));
    __half2 ha1 = __floats2half2_rn(sigmoidf_(s.z), sigmoidf_(s.w));
    uint2 px = {*(uint32_t*)&hx0, *(uint32_t*)&hx1};
    uint2 pa = {*(uint32_t*)&ha0, *(uint32_t*)&ha1};
    *(uint2*)&g_h_h[(size_t)node * 128 + q * 4] = px;
    *(uint2*)&g_h_h[(size_t)node * 128 + 64 + q * 4] = pa;

    float4 w0 = *(const float4*)&watt[q * 4];
    float4 w1 = *(const float4*)&watt[64 + q * 4];
    float p0 = s.x * w0.x + s.y * w0.y + s.z * w0.z + s.w * w0.w;
    float p1 = s.x * w1.x + s.y * w1.y + s.z * w1.z + s.w * w1.w;
    float p2 = r0.x * r0.x + r0.y * r0.y + r1.x * r1.x + r1.y * r1.y;
#pragma unroll
    for (int o = 8; o; o >>= 1) {
        p0 += __shfl_xor_sync(0xffffffffu, p0, o);
        p1 += __shfl_xor_sync(0xffffffffu, p1, o);
        p2 += __shfl_xor_sync(0xffffffffu, p2, o);
    }
    if (q == 0) {
        g_si[node] = p0;
        g_scal[node] = make_float2(p2, p1);   // {nsq, sj}
    }
}

// ---------------- cross-attn + self-attn via f16 tensor-core Gram ----------------
#define ATW 36
__global__ void __launch_bounds__(128) attn_kernel(const int* __restrict__ nbr1,
                                                   const int* __restrict__ nbr2) {
    __shared__ uint32_t sm[4][2 * 16 * ATW];
    int warp = threadIdx.x >> 5;
    int lane = threadIdx.x & 31;
    int i = blockIdx.x * 4 + warp;
    uint32_t* a1s = sm[warp];
    uint32_t* a2s = sm[warp] + 16 * ATW;

    int nid;
    if (lane < 16) nid = nbr1[i * 16 + lane];
    else           nid = nbr2[i * 16 + (lane - 16)];
    int gnid = (lane < 16) ? nid : NN + nid;

    uint32_t sbase = (uint32_t)__cvta_generic_to_shared(sm[warp]);
#pragma unroll
    for (int it = 0; it < 8; it++) {
        int idx = it * 32 + lane;
        int arr = idx >> 7;
        int local = idx & 127;
        int row = local >> 3, d4 = local & 7;
        int j = __shfl_sync(0xffffffffu, nid, arr * 16 + row);
        cp16(sbase + (uint32_t)(arr * 16 * ATW + row * ATW + d4 * 4) * 4,
             (const char*)g_aggr_h + ((size_t)(arr ? NN : 0) + j) * 128 + d4 * 16);
    }
    asm volatile("cp.async.commit_group;");
    float2 sc = __ldcg(&g_scal[gnid]);
    float myNsq = sc.x;
    asm volatile("cp.async.wait_group 0;" ::: "memory");
    __syncwarp();

    int rq = lane >> 2;
    int kq = lane & 3;
    int lr = lane & 7, lg = lane >> 3;
    float acc[2][4];
#pragma unroll
    for (int nt = 0; nt < 2; nt++)
#pragma unroll
        for (int c = 0; c < 4; c++) acc[nt][c] = 0.f;

#pragma unroll
    for (int ks = 0; ks < 4; ks++) {
        int kb = ks * 8;
        uint32_t a[4], b[2][2];
        ldm_x4(a, &a1s[(lr + (lg & 1) * 8) * ATW + kb + (lg >> 1) * 4]);
        ldm_x4(&b[0][0], &a2s[(lr + (lg >> 1) * 8) * ATW + kb + (lg & 1) * 4]);
        mma_f16(acc[0], a, b[0][0], b[0][1]);
        mma_f16(acc[1], a, b[1][0], b[1][1]);
    }

    float nsqK0 = __shfl_sync(0xffffffffu, myNsq, rq);
    float nsqK1 = __shfl_sync(0xffffffffu, myNsq, rq + 8);
    float rp0 = 0.f, rp1 = 0.f;
    float cp[2][2];
#pragma unroll
    for (int nt = 0; nt < 2; nt++) {
        float nsqL0 = __shfl_sync(0xffffffffu, myNsq, 16 + nt * 8 + 2 * kq);
        float nsqL1 = __shfl_sync(0xffffffffu, myNsq, 16 + nt * 8 + 2 * kq + 1);
        float d00 = fmaxf(nsqK0 + nsqL0 - 2.f * acc[nt][0], 1e-12f);
        float d01 = fmaxf(nsqK0 + nsqL1 - 2.f * acc[nt][1], 1e-12f);
        float d10 = fmaxf(nsqK1 + nsqL0 - 2.f * acc[nt][2], 1e-12f);
        float d11 = fmaxf(nsqK1 + nsqL1 - 2.f * acc[nt][3], 1e-12f);
        float s00 = __expf(-fsqrt_fast(d00));
        float s01 = __expf(-fsqrt_fast(d01));
        float s10 = __expf(-fsqrt_fast(d10));
        float s11 = __expf(-fsqrt_fast(d11));
        rp0 += s00 + s01;
        rp1 += s10 + s11;
        cp[nt][0] = s00 + s10;
        cp[nt][1] = s01 + s11;
    }

    rp0 += __shfl_xor_sync(0xffffffffu, rp0, 1);
    rp1 += __shfl_xor_sync(0xffffffffu, rp1, 1);
    rp0 += __shfl_xor_sync(0xffffffffu, rp0, 2);
    rp1 += __shfl_xor_sync(0xffffffffu, rp1, 2);
    float tot = rp0 + rp1;
#pragma unroll
    for (int o = 4; o <= 16; o <<= 1) tot += __shfl_xor_sync(0xffffffffu, tot, o);
#pragma unroll
    for (int o = 4; o <= 16; o <<= 1) {
        cp[0][0] += __shfl_xor_sync(0xffffffffu, cp[0][0], o);
        cp[0][1] += __shfl_xor_sync(0xffffffffu, cp[0][1], o);
        cp[1][0] += __shfl_xor_sync(0xffffffffu, cp[1][0], o);
        cp[1][1] += __shfl_xor_sync(0xffffffffu, cp[1][1], o);
    }

    int kl = lane & 15;
    float r0v = __shfl_sync(0xffffffffu, rp0, 4 * (kl & 7));
    float r1v = __shfl_sync(0xffffffffu, rp1, 4 * (kl & 7));
    float rowval = (kl < 8) ? r0v : r1v;
    int srcC = (kl & 7) >> 1;
    float c00 = __shfl_sync(0xffffffffu, cp[0][0], srcC);
    float c01 = __shfl_sync(0xffffffffu, cp[0][1], srcC);
    float c10 = __shfl_sync(0xffffffffu, cp[1][0], srcC);
    float c11 = __shfl_sync(0xffffffffu, cp[1][1], srcC);
    float colval = (kl >> 3) ? ((kl & 1) ? c11 : c10) : ((kl & 1) ? c01 : c00);

    float cross = __fdividef((lane < 16) ? rowval : colval, tot);

    float sii = (lane < 16) ? g_si[i] : g_si[NN + i];
    float sjv = sc.y;
    float zz = sii + sjv;
    float lr2 = (zz >= 0.f) ? zz : 0.01f * zz;
    float e = __expf(lr2);
    float esum = e;
#pragma unroll
    for (int o = 8; o; o >>= 1) esum += __shfl_xor_sync(0xffffffffu, esum, o);

    float nrm = cross * __fdividef(e, esum);
    if (lane < 16) g_norm[(size_t)i * 16 + lane] = nrm;
    else           g_norm[(size_t)(NN + i) * 16 + (lane - 16)] = nrm;
}

// ---------------- final weighted aggregate + sigmoid -> output ----------------
__global__ void out_kernel(const int* __restrict__ nbr1, const int* __restrict__ nbr2,
                           float* __restrict__ out) {
    int t = threadIdx.x;
    int nodeLocal = t >> 4;
    int q = t & 15;
    int node = blockIdx.x * 16 + nodeLocal;
    int g = node >= NN;
    int i = g ? node - NN : node;
    const int* nbr = g ? nbr2 : nbr1;
    size_t gbase = (size_t)g * NN;

    int nid = __ldg(&nbr[i * 16 + q]);
    float wq = __ldcg(&g_norm[(size_t)node * 16 + q]);

    float4 s = {0.f, 0.f, 0.f, 0.f};
#pragma unroll
    for (int k = 0; k < 16; k++) {
        int j = __shfl_sync(0xffffffffu, nid, k, 16);
        float w = __shfl_sync(0xffffffffu, wq, k, 16);
        uint2 raw = __ldcg((const uint2*)&g_yn_h[(gbase + j) * 64 + q * 4]);
        float2 lo = __half22float2(*(__half2*)&raw.x);
        float2 hi = __half22float2(*(__half2*)&raw.y);
        s.x += w * lo.x; s.y += w * lo.y; s.z += w * hi.x; s.w += w * hi.y;
    }

    float4 ys = __ldcg((const float4*)&g_ys[(size_t)node * 64 + q * 4]);
    float4 o0 = {sigmoidf_(ys.x), sigmoidf_(ys.y), sigmoidf_(ys.z), sigmoidf_(ys.w)};
    float4 o1 = {sigmoidf_(s.x), sigmoidf_(s.y), sigmoidf_(s.z), sigmoidf_(s.w)};
    *(float4*)&out[(size_t)node * 128 + q * 4] = o0;
    *(float4*)&out[(size_t)node * 128 + 64 + q * 4] = o1;
}

// ---------------- launch ----------------
extern "C" void kernel_launch(void* const* d_in, const int* in_sizes, int n_in,
                              void* d_out, int out_size) {
    const float* x1   = (const float*)d_in[0];
    const float* x2   = (const float*)d_in[1];
    const int*   nbr1 = (const int*)d_in[2];
    const int*   nbr2 = (const int*)d_in[3];
    const float* We1  = (const float*)d_in[4];
    const float* Ws1  = (const float*)d_in[5];
    const float* We2  = (const float*)d_in[6];
    const float* Ws2  = (const float*)d_in[7];
    const float* watt = (const float*)d_in[8];
    float* out = (float*)d_out;

    static cudaStream_t s_side = 0;
    static cudaEvent_t evF = 0, evJ = 0;
    static int smode = 0;
    if (smode == 0) {
        if (cudaStreamCreateWithFlags(&s_side, cudaStreamNonBlocking) == cudaSuccess &&
            cudaEventCreateWithFlags(&evF, cudaEventDisableTiming) == cudaSuccess &&
            cudaEventCreateWithFlags(&evJ, cudaEventDisableTiming) == cudaSuccess)
            smode = 1;
        else
            smode = -1;
    }

    cudaFuncSetAttribute(gemm_tc, cudaFuncAttributeMaxDynamicSharedMemorySize, GEMM_SMEM);

    pack_B_kernel<<<64, 256>>>(We1, Ws1, We2, Ws2);

    int gb = (2 * NN + 127) / 128;
    gemm_tc<<<gb, 256, GEMM_SMEM>>>(x1, x2, 1);

    aggr_kernel<<<(2 * NN) / 16, 256>>>(nbr1, nbr2, watt);

    if (smode == 1) {
        cudaEventRecord(evF, 0);
        cudaStreamWaitEvent(s_side, evF, 0);
        attn_kernel<<<NN / 4, 128, 0, s_side>>>(nbr1, nbr2);
        cudaEventRecord(evJ, s_side);
        gemm_tc<<<gb, 256, GEMM_SMEM>>>(x1, x2, 2);
        cudaStreamWaitEvent(0, evJ, 0);
    } else {
        attn_kernel<<<NN / 4, 128>>>(nbr1, nbr2);
        gemm_tc<<<gb, 256, GEMM_SMEM>>>(x1, x2, 2);
    }

    out_kernel<<<(2 * NN) / 16, 256>>>(nbr1, nbr2, out);
}